// round 6
// baseline (speedup 1.0000x reference)
#include <cuda_runtime.h>
#include <cuda_fp16.h>
#include <cstdint>
#include <math.h>

// ---------------------------------------------------------------------------
// Problem constants
// ---------------------------------------------------------------------------
#define BATCH   4096
#define DIN     128
#define DOUT    128
#define NB      9
#define KSPLIT  4
#define ISL     (DIN / KSPLIT)    // 32 input dims per block
#define KSLICE  (ISL * NB)        // 288 k per block
#define BM      64
#define NTILE   (BATCH / BM)      // 64
#define FCH     16                // input dims per feat chunk (144 k = 9 k16-steps)
#define NCH     (ISL / FCH)       // 2

// smem strides in halves; both give conflict-free ldmatrix row patterns
// (row stride in 4B words mod 32 must be 4*odd: 152h=76w -> 12; 296h=148w -> 20)
#define ASTR    152
#define BSTR    296

// smem layout (bytes)
#define OFF_XS  0
#define XS_B    (BM * 33 * 4)               // 8448
#define OFF_BS  (OFF_XS + XS_B)
#define BS_B    (DOUT * BSTR * 2)           // 75776
#define OFF_AS  (OFF_BS + BS_B)
#define AS_B    (BM * ASTR * 2)             // 19456
#define OFF_BP  (OFF_AS + AS_B)
#define BP_B    (2 * DOUT * 4)              // 1024
#define SMEM_BYTES (OFF_BP + BP_B)          // 104704 -> 2 CTAs/SM

// ---------------------------------------------------------------------------
// Device scratch (allocation-free)
// ---------------------------------------------------------------------------
__device__ float g_part[KSPLIT * BATCH * DOUT];   // 8 MB fp32 partials
__device__ int   g_cnt[NTILE];                    // zero-init; reset by reducer

// ---------------------------------------------------------------------------
// Helpers
// ---------------------------------------------------------------------------
__device__ __forceinline__ float tanh_ap(float f) {
    float r; asm("tanh.approx.f32 %0, %1;" : "=f"(r) : "f"(f)); return r;
}
__device__ __forceinline__ float sqrt_ap(float f) {
    float r; asm("sqrt.approx.f32 %0, %1;" : "=f"(r) : "f"(f)); return r;
}
__device__ __forceinline__ uint32_t s2u(const void* p) {
    uint32_t a;
    asm("{ .reg .u64 t; cvta.to.shared.u64 t, %1; cvt.u32.u64 %0, t; }" : "=r"(a) : "l"(p));
    return a;
}
__device__ __forceinline__ void ldm_x4(uint32_t* r, uint32_t addr) {
    asm volatile("ldmatrix.sync.aligned.m8n8.x4.shared.b16 {%0,%1,%2,%3}, [%4];"
        : "=r"(r[0]), "=r"(r[1]), "=r"(r[2]), "=r"(r[3]) : "r"(addr));
}
// m16n8k16 fp16 mma, fp32 accumulate
__device__ __forceinline__ void mma_f16(float* d, const uint32_t* a, uint32_t b0, uint32_t b1) {
    asm volatile(
        "mma.sync.aligned.m16n8k16.row.col.f32.f16.f16.f32 "
        "{%0,%1,%2,%3}, {%4,%5,%6,%7}, {%8,%9}, {%0,%1,%2,%3};"
        : "+f"(d[0]), "+f"(d[1]), "+f"(d[2]), "+f"(d[3])
        : "r"(a[0]), "r"(a[1]), "r"(a[2]), "r"(a[3]), "r"(b0), "r"(b1));
}

// ---------------------------------------------------------------------------
// Single fused kernel: per-block W*C conversion -> smem fp16 B-slice,
// fused basis feats -> fp16 A chunks, m16n8k16 mma, split-K partials,
// last-arriving split block reduces (bias folded into partials).
// Grid (64 tiles, 4 splits), 256 threads, 2 CTAs/SM.
// ---------------------------------------------------------------------------
__global__ __launch_bounds__(256, 2)
void kan_fused(const float* __restrict__ x, const float* __restrict__ W,
               const float* __restrict__ bias, const float* __restrict__ C,
               float* __restrict__ out)
{
    extern __shared__ char smem[];
    float*  Xs = (float*)(smem + OFF_XS);      // [64][33]
    __half* Bs = (__half*)(smem + OFF_BS);     // [128 n][296], cols 0..287 data
    __half* As = (__half*)(smem + OFF_AS);     // [64 m][152],  cols 0..143 data
    float*  Bp = (float*)(smem + OFF_BP);      // [2][128] beta partials
    __shared__ int s_last;

    const int tid   = threadIdx.x;
    const int lane  = tid & 31;
    const int warp  = tid >> 5;
    const int wm    = warp & 1;          // m warp -> m0 = wm*32
    const int wn    = warp >> 1;         // n warp -> n0 = wn*32
    const int g     = lane >> 2;
    const int tg    = lane & 3;
    const int tile  = blockIdx.x;
    const int split = blockIdx.y;
    const int bm0   = tile * BM;
    const int i0    = split * ISL;

    // --- stage X tile [64 rows][32 i]
    #pragma unroll
    for (int jj = 0; jj < 2; ++jj) {
        int j = tid + jj * 256;
        int r = j >> 3, q = j & 7;
        float4 v = *(const float4*)(x + (size_t)(bm0 + r) * DIN + i0 + q * 4);
        float* d = Xs + r * 33 + q * 4;
        d[0] = v.x; d[1] = v.y; d[2] = v.z; d[3] = v.w;
    }

    // --- convert W*C slice -> Bs fp16 [n][k=ii*9+kb]; also beta partials
    {
        const int o = tid & 127;
        const int h = tid >> 7;
        #pragma unroll 4
        for (int it = 0; it < 16; ++it) {
            int ii = it * 2 + h;
            const float* wp = W + ((size_t)(i0 + ii) * DOUT + o) * NB;
            float cv = C[(i0 + ii) * DOUT + o];
            __half* dp = Bs + o * BSTR + ii * NB;
            #pragma unroll
            for (int kb = 0; kb < NB; ++kb)
                dp[kb] = __float2half_rn(wp[kb] * cv);
        }
        float bsum = 0.0f;
        #pragma unroll 4
        for (int q = 0; q < 16; ++q) {
            int ii = h * 16 + q;
            bsum += bias[(i0 + ii) * DOUT + o] * C[(i0 + ii) * DOUT + o];
        }
        Bp[h * DOUT + o] = bsum;
    }

    // --- precompute ldmatrix lane addresses
    const int t4 = lane >> 3;            // tile index 0..3
    const int r8 = lane & 7;             // row within tile
    uint32_t aAddr[2], bAddr[2];
    {
        uint32_t asb = s2u(As), bsb = s2u(Bs);
        #pragma unroll
        for (int mt = 0; mt < 2; ++mt) {
            int row = wm * 32 + mt * 16 + (t4 & 1) * 8 + r8;
            aAddr[mt] = asb + (uint32_t)(row * ASTR + (t4 >> 1) * 8) * 2;
        }
        #pragma unroll
        for (int p = 0; p < 2; ++p) {
            int n = wn * 32 + p * 16 + (t4 >> 1) * 8 + r8;
            bAddr[p] = bsb + (uint32_t)(n * BSTR + (t4 & 1) * 8) * 2;
        }
    }

    float acc[2][4][4];
    #pragma unroll
    for (int mt = 0; mt < 2; ++mt)
        #pragma unroll
        for (int nt = 0; nt < 4; ++nt)
            #pragma unroll
            for (int e = 0; e < 4; ++e) acc[mt][nt][e] = 0.0f;

    __syncthreads();   // Xs, Bs ready

    #pragma unroll
    for (int c = 0; c < NCH; ++c) {
        // --- feats: 16 dims x 64 rows, 4 per thread -> As[row][ii*9+kb] fp16
        #pragma unroll
        for (int jj = 0; jj < 4; ++jj) {
            int j   = tid + jj * 256;
            int row = j & 63;
            int ii  = j >> 6;            // 0..15
            float xv = Xs[row * 33 + c * FCH + ii];
            float ax = fabsf(xv);
            float x2 = xv * xv;
            __half* d = As + row * ASTR + ii * NB;
            d[0] = __float2half_rn(xv);
            d[1] = __float2half_rn(x2);
            d[2] = __float2half_rn(x2 * xv);
            d[3] = __float2half_rn(__expf(xv));
            d[4] = __float2half_rn(__logf(ax + 1.0f));
            d[5] = __float2half_rn(sqrt_ap(ax));
            d[6] = __float2half_rn(tanh_ap(xv));
            d[7] = __float2half_rn(__sinf(xv));
            d[8] = __float2half_rn(ax);
        }
        __syncthreads();

        // --- 9 k16-steps
        #pragma unroll
        for (int s9 = 0; s9 < 9; ++s9) {
            const uint32_t kc = (uint32_t)(s9 * 16) * 2;            // bytes in As
            const uint32_t kB = (uint32_t)((c * 9 + s9) * 16) * 2;  // bytes in Bs
            uint32_t a[2][4], bq[2][4];
            ldm_x4(a[0], aAddr[0] + kc);
            ldm_x4(a[1], aAddr[1] + kc);
            ldm_x4(bq[0], bAddr[0] + kB);
            ldm_x4(bq[1], bAddr[1] + kB);
            #pragma unroll
            for (int mt = 0; mt < 2; ++mt)
                #pragma unroll
                for (int nt = 0; nt < 4; ++nt)
                    mma_f16(acc[mt][nt], a[mt], bq[nt >> 1][(nt & 1) * 2],
                                                 bq[nt >> 1][(nt & 1) * 2 + 1]);
        }
        __syncthreads();
    }

    // --- epilogue: add this split's beta, write partials
    {
        float* base = g_part + (size_t)split * BATCH * DOUT;
        #pragma unroll
        for (int nt = 0; nt < 4; ++nt) {
            int col = wn * 32 + nt * 8 + tg * 2;
            float b0 = Bp[col]     + Bp[DOUT + col];
            float b1 = Bp[col + 1] + Bp[DOUT + col + 1];
            #pragma unroll
            for (int mt = 0; mt < 2; ++mt) {
                int row = bm0 + wm * 32 + mt * 16 + g;
                float* p = base + (size_t)row * DOUT + col;
                *(float2*)p              = make_float2(acc[mt][nt][0] + b0, acc[mt][nt][1] + b1);
                *(float2*)(p + 8 * DOUT) = make_float2(acc[mt][nt][2] + b0, acc[mt][nt][3] + b1);
            }
        }
    }

    // --- last split block of this tile reduces 4 partial planes -> out
    __threadfence();
    __syncthreads();
    if (tid == 0)
        s_last = (atomicAdd(&g_cnt[tile], 1) == KSPLIT - 1);
    __syncthreads();

    if (s_last) {
        __threadfence();
        const float4* pp = (const float4*)g_part;
        const size_t plane = (size_t)BATCH * DOUT / 4;
        const size_t base4 = (size_t)bm0 * (DOUT / 4);
        #pragma unroll
        for (int idx = tid; idx < BM * DOUT / 4; idx += 256) {
            size_t o = base4 + idx;
            float4 p0 = __ldcg(pp + o);
            float4 p1 = __ldcg(pp + plane + o);
            float4 p2 = __ldcg(pp + 2 * plane + o);
            float4 p3 = __ldcg(pp + 3 * plane + o);
            float4 s;
            s.x = (p0.x + p1.x) + (p2.x + p3.x);
            s.y = (p0.y + p1.y) + (p2.y + p3.y);
            s.z = (p0.z + p1.z) + (p2.z + p3.z);
            s.w = (p0.w + p1.w) + (p2.w + p3.w);
            ((float4*)out)[o] = s;
        }
        __syncthreads();
        if (tid == 0) g_cnt[tile] = 0;   // reset for next graph replay
    }
}

// ---------------------------------------------------------------------------
extern "C" void kernel_launch(void* const* d_in, const int* in_sizes, int n_in,
                              void* d_out, int out_size) {
    const float* x    = (const float*)d_in[0];   // [4096,128]
    const float* W    = (const float*)d_in[1];   // [128,128,9]
    const float* bias = (const float*)d_in[2];   // [128,128]
    const float* C    = (const float*)d_in[3];   // [128,128]
    float* out        = (float*)d_out;           // [4096,128]
    (void)in_sizes; (void)n_in; (void)out_size;

    cudaFuncSetAttribute(kan_fused, cudaFuncAttributeMaxDynamicSharedMemorySize, SMEM_BYTES);
    kan_fused<<<dim3(NTILE, KSPLIT), 256, SMEM_BYTES>>>(x, W, bias, C, out);
}

// round 7
// speedup vs baseline: 1.7805x; 1.7805x over previous
#include <cuda_runtime.h>
#include <cuda_fp16.h>
#include <cstdint>
#include <math.h>

// ---------------------------------------------------------------------------
// Problem constants
// ---------------------------------------------------------------------------
#define BATCH   4096
#define DIN     128
#define DOUT    128
#define NB      9
#define KPAD    10                 // k per input dim, padded 9 -> 10 (slot 9 = 0)
#define KTOT    (DIN * KPAD)       // 1280
#define KSPLIT  4
#define ISL     (DIN / KSPLIT)     // 32 input dims per split
#define KSLICE  (ISL * KPAD)       // 320 k per split
#define BM      64
#define NTILE   (BATCH / BM)       // 64
#define FCH     8                  // input dims per feat chunk
#define NCH     (ISL / FCH)        // 4 chunks
#define KCH     (FCH * KPAD)       // 80 k rows per chunk (5 k16-steps)

// smem strides (halves). ASTR: 72h=144B=36w === 4 banks apart per row -> CF.
// BSTR: 328h=656B=164w === 4 banks apart per row -> CF. 656 % 16 == 0 (cp.async).
#define ASTR    72
#define BSTR    328

// smem layout (bytes)
#define OFF_XS  0
#define XS_B    (BM * 33 * 4)               // 8448
#define OFF_BS  (OFF_XS + XS_B)
#define BS_B    (DOUT * BSTR * 2)           // 83968
#define OFF_AS  (OFF_BS + BS_B)
#define AS_B    (KCH * ASTR * 2)            // 11520
#define OFF_BP  (OFF_AS + AS_B)
#define BP_B    (DOUT * 4)                  // 512
#define SMEM_BYTES (OFF_BP + BP_B)          // 104448 -> 2 CTAs/SM

// ---------------------------------------------------------------------------
// Device scratch (allocation-free)
// ---------------------------------------------------------------------------
__device__ __half g_Wh[DOUT * KTOT];              // fp16 W*C, [o][k], 320 KB
__device__ float  g_part[KSPLIT * BATCH * DOUT];  // 8 MB fp32 partials
__device__ int    g_cnt[NTILE];                   // zero-init; reset by reducer

// ---------------------------------------------------------------------------
// Helpers
// ---------------------------------------------------------------------------
__device__ __forceinline__ float tanh_ap(float f) {
    float r; asm("tanh.approx.f32 %0, %1;" : "=f"(r) : "f"(f)); return r;
}
__device__ __forceinline__ float sqrt_ap(float f) {
    float r; asm("sqrt.approx.f32 %0, %1;" : "=f"(r) : "f"(f)); return r;
}
__device__ __forceinline__ uint32_t s2u(const void* p) {
    uint32_t a;
    asm("{ .reg .u64 t; cvta.to.shared.u64 t, %1; cvt.u32.u64 %0, t; }" : "=r"(a) : "l"(p));
    return a;
}
__device__ __forceinline__ void cp16(uint32_t dst, const void* src) {
    asm volatile("cp.async.cg.shared.global [%0], [%1], 16;" :: "r"(dst), "l"(src) : "memory");
}
#define CP_COMMIT() asm volatile("cp.async.commit_group;" ::: "memory")
#define CP_WAIT0()  asm volatile("cp.async.wait_group 0;"  ::: "memory")

__device__ __forceinline__ void ldm_x4(uint32_t* r, uint32_t addr) {
    asm volatile("ldmatrix.sync.aligned.m8n8.x4.shared.b16 {%0,%1,%2,%3}, [%4];"
        : "=r"(r[0]), "=r"(r[1]), "=r"(r[2]), "=r"(r[3]) : "r"(addr));
}
__device__ __forceinline__ void ldm_x4t(uint32_t* r, uint32_t addr) {
    asm volatile("ldmatrix.sync.aligned.m8n8.x4.trans.shared.b16 {%0,%1,%2,%3}, [%4];"
        : "=r"(r[0]), "=r"(r[1]), "=r"(r[2]), "=r"(r[3]) : "r"(addr));
}
// m16n8k16 fp16 mma, fp32 accumulate
__device__ __forceinline__ void mma_f16(float* d, const uint32_t* a, uint32_t b0, uint32_t b1) {
    asm volatile(
        "mma.sync.aligned.m16n8k16.row.col.f32.f16.f16.f32 "
        "{%0,%1,%2,%3}, {%4,%5,%6,%7}, {%8,%9}, {%0,%1,%2,%3};"
        : "+f"(d[0]), "+f"(d[1]), "+f"(d[2]), "+f"(d[3])
        : "r"(a[0]), "r"(a[1]), "r"(a[2]), "r"(a[3]), "r"(b0), "r"(b1));
}

// ---------------------------------------------------------------------------
// Prep: g_Wh[o][i*10 + 2p .. 2p+1] = fp16(W[i,o,kb]*C[i,o]); slot 9 = 0.
// One thread per (i, o, kb-pair p): 81920 threads -> latency fully hidden.
// ---------------------------------------------------------------------------
__global__ void kan_prep(const float* __restrict__ W, const float* __restrict__ C) {
    int j = blockIdx.x * blockDim.x + threadIdx.x;   // 0 .. 81919
    int p  = j % 5;
    int io = j / 5;                 // i*128 + o
    if (io >= DIN * DOUT) return;
    int o = io & 127;
    int i = io >> 7;
    float cv = C[io];
    const float* wp = W + (size_t)io * NB + p * 2;
    float v0 = wp[0] * cv;
    float v1 = (p < 4) ? wp[1] * cv : 0.0f;
    ((__half2*)g_Wh)[o * (KTOT / 2) + i * (KPAD / 2) + p] = __floats2half2_rn(v0, v1);
}

// ---------------------------------------------------------------------------
// Main: fused basis + fp16 ldmatrix mma, full B slice cp.async-prefetched,
// split-K over Din, per-split bias folded, fused last-block reduction.
// Grid (64 tiles, 4 splits), 256 threads (8 warps; warp tile 32m x 32n).
// ---------------------------------------------------------------------------
__global__ __launch_bounds__(256, 2)
void kan_main(const float* __restrict__ x, const float* __restrict__ bias,
              const float* __restrict__ C, float* __restrict__ out)
{
    extern __shared__ char smem[];
    float*  Xs = (float*)(smem + OFF_XS);      // [64][33]
    __half* Bs = (__half*)(smem + OFF_BS);     // [128 n][328], cols 0..319 data
    __half* As = (__half*)(smem + OFF_AS);     // [80 k][72], cols 0..63 data (k-major!)
    float*  Bp = (float*)(smem + OFF_BP);      // [128] beta partials for this split
    __shared__ int s_last;

    const int tid   = threadIdx.x;
    const int lane  = tid & 31;
    const int warp  = tid >> 5;
    const int wm    = warp & 1;          // m warp -> m0 = wm*32
    const int wn    = warp >> 1;         // n warp -> n0 = wn*32
    const int g     = lane >> 2;
    const int tg    = lane & 3;
    const int t4    = lane >> 3;         // ldmatrix tile group 0..3
    const int r8    = lane & 7;
    const int tile  = blockIdx.x;
    const int split = blockIdx.y;
    const int bm0   = tile * BM;
    const int i0    = split * ISL;

    // --- cp.async the full fp16 B slice [128 n][320 k]: 5120 x 16B
    {
        const uint32_t bsb = s2u(Bs);
        const __half*  src0 = g_Wh + (size_t)split * KSLICE;
        #pragma unroll
        for (int jj = 0; jj < 20; ++jj) {
            int j = tid + jj * 256;
            int n = j / 40, q = j - n * 40;
            cp16(bsb + (uint32_t)(n * (BSTR * 2) + q * 16),
                 src0 + (size_t)n * KTOT + q * 8);
        }
        CP_COMMIT();
    }

    // --- stage X tile [64 rows][32 i]
    #pragma unroll
    for (int jj = 0; jj < 2; ++jj) {
        int j = tid + jj * 256;
        int r = j >> 3, q = j & 7;
        float4 v = *(const float4*)(x + (size_t)(bm0 + r) * DIN + i0 + q * 4);
        float* d = Xs + r * 33 + q * 4;
        d[0] = v.x; d[1] = v.y; d[2] = v.z; d[3] = v.w;
    }

    // --- this split's beta slice: Bp[o] = sum_{i in split} bias[i,o]*C[i,o]
    if (tid < DOUT) {
        float s = 0.0f;
        #pragma unroll 8
        for (int ii = 0; ii < ISL; ++ii)
            s += bias[(i0 + ii) * DOUT + tid] * C[(i0 + ii) * DOUT + tid];
        Bp[tid] = s;
    }

    // --- precompute ldmatrix lane base addresses
    uint32_t aAddr[2], bAddr[2];
    {
        const uint32_t asb = s2u(As), bsb = s2u(Bs);
        // A (trans, from [k][m]): group t -> rows k0+(t>>1)*8+r8, col m0+(t&1)*8
        #pragma unroll
        for (int mt = 0; mt < 2; ++mt) {
            int m0 = wm * 32 + mt * 16;
            aAddr[mt] = asb + (uint32_t)(((t4 >> 1) * 8 + r8) * ASTR + m0 + (t4 & 1) * 8) * 2;
        }
        // B (non-trans, from [n][k]): group t -> n-rows n0+(t>>1)*8+r8, k-col (t&1)*8
        #pragma unroll
        for (int p = 0; p < 2; ++p) {
            int n = wn * 32 + p * 16 + (t4 >> 1) * 8 + r8;
            bAddr[p] = bsb + (uint32_t)(n * BSTR + (t4 & 1) * 8) * 2;
        }
    }

    float acc[2][4][4];
    #pragma unroll
    for (int mt = 0; mt < 2; ++mt)
        #pragma unroll
        for (int nt = 0; nt < 4; ++nt)
            #pragma unroll
            for (int e = 0; e < 4; ++e) acc[mt][nt][e] = 0.0f;

    __syncthreads();   // Xs, Bp ready

    #pragma unroll
    for (int c = 0; c < NCH; ++c) {
        if (c) __syncthreads();   // previous chunk's ldmatrix reads of As done

        // --- feats: 8 dims x 64 rows, 2 tasks/thread -> As[k][row] fp16 (CF stores)
        #pragma unroll
        for (int jj = 0; jj < 2; ++jj) {
            int j   = tid + jj * 256;
            int row = j & 63;
            int ii  = j >> 6;            // 0..7
            float xv = Xs[row * 33 + c * FCH + ii];
            float ax = fabsf(xv);
            float x2 = xv * xv;
            __half* d = As + (ii * KPAD) * ASTR + row;
            d[0 * ASTR] = __float2half_rn(xv);
            d[1 * ASTR] = __float2half_rn(x2);
            d[2 * ASTR] = __float2half_rn(x2 * xv);
            d[3 * ASTR] = __float2half_rn(__expf(xv));
            d[4 * ASTR] = __float2half_rn(__logf(ax + 1.0f));
            d[5 * ASTR] = __float2half_rn(sqrt_ap(ax));
            d[6 * ASTR] = __float2half_rn(tanh_ap(xv));
            d[7 * ASTR] = __float2half_rn(__sinf(xv));
            d[8 * ASTR] = __float2half_rn(ax);
            d[9 * ASTR] = __half(0.0f);          // pad slot
        }
        if (c == 0) CP_WAIT0();   // B slice resident before first mma
        __syncthreads();

        // --- 5 k16-steps
        #pragma unroll
        for (int s5 = 0; s5 < 5; ++s5) {
            const uint32_t kaOff = (uint32_t)(s5 * 16 * ASTR) * 2;          // bytes in As
            const uint32_t kbOff = (uint32_t)((c * KCH + s5 * 16)) * 2;     // bytes in Bs
            uint32_t a[2][4], bq[2][4];
            ldm_x4t(a[0], aAddr[0] + kaOff);
            ldm_x4t(a[1], aAddr[1] + kaOff);
            ldm_x4(bq[0], bAddr[0] + kbOff);
            ldm_x4(bq[1], bAddr[1] + kbOff);
            #pragma unroll
            for (int mt = 0; mt < 2; ++mt)
                #pragma unroll
                for (int nt = 0; nt < 4; ++nt)
                    mma_f16(acc[mt][nt], a[mt],
                            bq[nt >> 1][(nt & 1) * 2], bq[nt >> 1][(nt & 1) * 2 + 1]);
        }
    }

    // --- epilogue: add this split's beta, write partials
    {
        float* base = g_part + (size_t)split * BATCH * DOUT;
        #pragma unroll
        for (int nt = 0; nt < 4; ++nt) {
            int col = wn * 32 + nt * 8 + tg * 2;
            float b0 = Bp[col];
            float b1 = Bp[col + 1];
            #pragma unroll
            for (int mt = 0; mt < 2; ++mt) {
                int row = bm0 + wm * 32 + mt * 16 + g;
                float* p = base + (size_t)row * DOUT + col;
                *(float2*)p              = make_float2(acc[mt][nt][0] + b0, acc[mt][nt][1] + b1);
                *(float2*)(p + 8 * DOUT) = make_float2(acc[mt][nt][2] + b0, acc[mt][nt][3] + b1);
            }
        }
    }

    // --- last split block of this tile reduces 4 partial planes -> out
    __threadfence();
    __syncthreads();
    if (tid == 0)
        s_last = (atomicAdd(&g_cnt[tile], 1) == KSPLIT - 1);
    __syncthreads();

    if (s_last) {
        __threadfence();
        const float4* pp = (const float4*)g_part;
        const size_t plane = (size_t)BATCH * DOUT / 4;
        const size_t base4 = (size_t)bm0 * (DOUT / 4);
        #pragma unroll
        for (int idx = tid; idx < BM * DOUT / 4; idx += 256) {
            size_t o = base4 + idx;
            float4 p0 = __ldcg(pp + o);
            float4 p1 = __ldcg(pp + plane + o);
            float4 p2 = __ldcg(pp + 2 * plane + o);
            float4 p3 = __ldcg(pp + 3 * plane + o);
            float4 s;
            s.x = (p0.x + p1.x) + (p2.x + p3.x);
            s.y = (p0.y + p1.y) + (p2.y + p3.y);
            s.z = (p0.z + p1.z) + (p2.z + p3.z);
            s.w = (p0.w + p1.w) + (p2.w + p3.w);
            ((float4*)out)[o] = s;
        }
        __syncthreads();
        if (tid == 0) g_cnt[tile] = 0;   // reset for next graph replay
    }
}

// ---------------------------------------------------------------------------
extern "C" void kernel_launch(void* const* d_in, const int* in_sizes, int n_in,
                              void* d_out, int out_size) {
    const float* x    = (const float*)d_in[0];   // [4096,128]
    const float* W    = (const float*)d_in[1];   // [128,128,9]
    const float* bias = (const float*)d_in[2];   // [128,128]
    const float* C    = (const float*)d_in[3];   // [128,128]
    float* out        = (float*)d_out;           // [4096,128]
    (void)in_sizes; (void)n_in; (void)out_size;

    cudaFuncSetAttribute(kan_main, cudaFuncAttributeMaxDynamicSharedMemorySize, SMEM_BYTES);

    kan_prep<<<320, 256>>>(W, C);
    kan_main<<<dim3(NTILE, KSPLIT), 256, SMEM_BYTES>>>(x, bias, C, out);
}